// round 10
// baseline (speedup 1.0000x reference)
#include <cuda_runtime.h>
#include <cuda_bf16.h>
#include <cstdint>

// costs[0,i,j] = 0.5*(|x_i|^2 + |y_j|^2) - x_i . y_j
// x: [1,4096,128] f32, y: [1,4096,128] f32, out: [1,4096,4096] f32.
//
// bf16 mma.sync m16n8k16 + ldmatrix, swizzled smem, pre-converted bf16
// operands, 256 thr / 8 warps x (64x32), 2 CTAs/SM, and a 4-deep k-chunked
// cp.async pipeline so MMAs start after 1/4 of the fill.

#define NROWS 4096
#define DK    128
#define TILE  128

static __device__ float g_x2[NROWS];
static __device__ float g_y2[NROWS];
static __device__ __align__(16) __nv_bfloat16 g_xb[NROWS * DK];
static __device__ __align__(16) __nv_bfloat16 g_yb[NROWS * DK];

// ---- helpers ----
__device__ __forceinline__ uint32_t pack_bf16x2(float a, float b) {
    uint32_t r;
    asm("cvt.rn.bf16x2.f32 %0, %1, %2;" : "=r"(r) : "f"(b), "f"(a));
    return r;
}

__device__ __forceinline__ uint32_t smem_u32(const void* p) {
    uint32_t a;
    asm("{ .reg .u64 t; cvta.to.shared.u64 t, %1; cvt.u32.u64 %0, t; }" : "=r"(a) : "l"(p));
    return a;
}

__device__ __forceinline__ void ldsm4(uint32_t* r, uint32_t addr) {
    asm volatile("ldmatrix.sync.aligned.m8n8.x4.shared.b16 {%0,%1,%2,%3}, [%4];"
                 : "=r"(r[0]), "=r"(r[1]), "=r"(r[2]), "=r"(r[3]) : "r"(addr));
}

__device__ __forceinline__ void mma16(float* d, const uint32_t* a, uint32_t b0, uint32_t b1) {
    asm volatile(
        "mma.sync.aligned.m16n8k16.row.col.f32.bf16.bf16.f32 "
        "{%0,%1,%2,%3}, {%4,%5,%6,%7}, {%8,%9}, {%0,%1,%2,%3};"
        : "+f"(d[0]), "+f"(d[1]), "+f"(d[2]), "+f"(d[3])
        : "r"(a[0]), "r"(a[1]), "r"(a[2]), "r"(a[3]), "r"(b0), "r"(b1));
}

__device__ __forceinline__ void cp16(uint32_t dst, const void* src) {
    asm volatile("cp.async.cg.shared.global [%0], [%1], 16;" :: "r"(dst), "l"(src) : "memory");
}

// ---- smem layout (bytes) ----
#define SM_YS    0
#define SM_A     512
#define SM_B     (512 + TILE * 256)
#define SM_TOTAL (512 + 2 * TILE * 256)

// ---- pre-kernel: row norms + bf16 conversion (one pass) ----
__global__ void prep_kernel(const float* __restrict__ x, const float* __restrict__ y) {
    int gid = blockIdx.x * blockDim.x + threadIdx.x;
    int row = gid >> 5;
    int lane = gid & 31;
    bool isx = row < NROWS;
    int r = isx ? row : row - NROWS;
    const float4 v = ((const float4*)(isx ? x : y))[(size_t)r * 32 + lane];
    float s = v.x * v.x + v.y * v.y + v.z * v.z + v.w * v.w;
#pragma unroll
    for (int o = 16; o; o >>= 1) s += __shfl_xor_sync(0xffffffffu, s, o);
    uint2 w;
    w.x = pack_bf16x2(v.x, v.y);
    w.y = pack_bf16x2(v.z, v.w);
    ((uint2*)(isx ? g_xb : g_yb))[(size_t)r * 32 + lane] = w;
    if (lane == 0) { if (isx) g_x2[r] = s; else g_y2[r] = s; }
}

// ---- main kernel: 128x128 tile/CTA, 8 warps (2M x 4N of 64x32) ----
__global__ void __launch_bounds__(256, 2)
cost_kernel(float* __restrict__ out) {
    extern __shared__ char smem[];
    float* ys = (float*)(smem + SM_YS);
    const uint32_t smem_base = smem_u32(smem);

    const int tid = threadIdx.x;
    const int wid = tid >> 5;
    const int lane = tid & 31;

    const int m0 = blockIdx.y * TILE;
    const int n0 = blockIdx.x * TILE;

    if (tid < 128) ys[tid] = 0.5f * g_y2[n0 + tid];

    // k-chunked fill: chunk c covers 16B-units cu = 4c..4c+3 (k = 32c..32c+31)
    // for BOTH tiles. 1024 units per chunk / 256 thr = 4 cp16 each, then commit.
#pragma unroll
    for (int c = 0; c < 4; c++) {
#pragma unroll
        for (int i = 0; i < 4; i++) {
            int flat = tid + 256 * i;              // 0..1023
            int isB  = flat >> 9;
            int u    = flat & 511;
            int row  = u >> 2;                     // 0..127
            int cu   = c * 4 + (u & 3);            // 16B unit in row
            const uint4* src = (const uint4*)(isB ? g_yb : g_xb)
                               + (size_t)((isB ? n0 : m0) + row) * 16 + cu;
            uint32_t dst = smem_base + (isB ? SM_B : SM_A)
                           + row * 256 + ((cu ^ (row & 7)) << 4);
            cp16(dst, src);
        }
        asm volatile("cp.async.commit_group;" ::: "memory");
    }

    // Warp tiling: w_m 0..1 (64 rows), w_n 0..3 (32 cols)
    const int w_m = wid >> 2, w_n = wid & 3;

    const int a_row0 = w_m * 64 + (lane & 7) + ((lane >> 3) & 1) * 8;
    const int a_sel  = lane >> 4;
    const int b_row0 = w_n * 32 + (lane & 7) + (lane >> 4) * 8;
    const int b_sel  = (lane >> 3) & 1;

    const uint32_t aBase = smem_base + SM_A + a_row0 * 256;
    const uint32_t bBase0 = smem_base + SM_B + b_row0 * 256;
    const uint32_t bBase1 = bBase0 + 16 * 256;
    const int a_ph = a_row0 & 7;
    const int b_ph = b_row0 & 7;

    float acc[4][4][4];
#pragma unroll
    for (int ti = 0; ti < 4; ti++)
#pragma unroll
        for (int j = 0; j < 4; j++)
#pragma unroll
            for (int r = 0; r < 4; r++) acc[ti][j][r] = 0.f;

    // Mainloop, consuming one k-chunk (2 k-steps) at a time.
#define K_CHUNK(c, WAITN)                                                     \
    {                                                                         \
        asm volatile("cp.async.wait_group " #WAITN ";" ::: "memory");         \
        __syncthreads();                                                      \
        _Pragma("unroll")                                                     \
        for (int ks = 2 * (c); ks < 2 * (c) + 2; ks++) {                      \
            const uint32_t aoff = (uint32_t)(((ks * 2 + a_sel) ^ a_ph) << 4); \
            const uint32_t boff = (uint32_t)(((ks * 2 + b_sel) ^ b_ph) << 4); \
            uint32_t a[4][4], b0[4], b1[4];                                   \
            ldsm4(b0, bBase0 + boff);                                         \
            ldsm4(b1, bBase1 + boff);                                         \
            _Pragma("unroll")                                                 \
            for (int ti = 0; ti < 4; ti++)                                    \
                ldsm4(a[ti], aBase + ti * (16 * 256) + aoff);                 \
            _Pragma("unroll")                                                 \
            for (int ti = 0; ti < 4; ti++) {                                  \
                mma16(acc[ti][0], a[ti], b0[0], b0[1]);                       \
                mma16(acc[ti][1], a[ti], b0[2], b0[3]);                       \
                mma16(acc[ti][2], a[ti], b1[0], b1[1]);                       \
                mma16(acc[ti][3], a[ti], b1[2], b1[3]);                       \
            }                                                                 \
        }                                                                     \
    }

    K_CHUNK(0, 3)
    K_CHUNK(1, 2)
    K_CHUNK(2, 1)
    K_CHUNK(3, 0)
#undef K_CHUNK

    // Epilogue: acc[ti][j] -> rows w_m*64+ti*16+{0,8}+gid, cols w_n*32+j*8+2*tig
    const int gid = lane >> 2, tig = lane & 3;
    const int mrow_base = m0 + w_m * 64;

#pragma unroll
    for (int ti = 0; ti < 4; ti++) {
#pragma unroll
        for (int h = 0; h < 2; h++) {
            const int m = mrow_base + ti * 16 + h * 8 + gid;
            const float xv = 0.5f * g_x2[m];
            float* orow = out + (size_t)m * NROWS + n0 + w_n * 32 + tig * 2;
#pragma unroll
            for (int j = 0; j < 4; j++) {
                const int col = w_n * 32 + j * 8 + tig * 2;
                float2 o;
                o.x = xv + ys[col + 0] - acc[ti][j][h * 2 + 0];
                o.y = xv + ys[col + 1] - acc[ti][j][h * 2 + 1];
                *(float2*)(orow + j * 8) = o;
            }
        }
    }
}

// ---- launch ----
extern "C" void kernel_launch(void* const* d_in, const int* in_sizes, int n_in,
                              void* d_out, int out_size) {
    const float* x = (const float*)d_in[0];
    const float* y = (const float*)d_in[1];
    float* out = (float*)d_out;

    cudaFuncSetAttribute(cost_kernel, cudaFuncAttributeMaxDynamicSharedMemorySize, SM_TOTAL);

    prep_kernel<<<(2 * NROWS * 32) / 256, 256>>>(x, y);
    dim3 grid(NROWS / TILE, NROWS / TILE);
    cost_kernel<<<grid, 256, SM_TOTAL>>>(out);
}

// round 11
// speedup vs baseline: 1.0654x; 1.0654x over previous
#include <cuda_runtime.h>
#include <cuda_bf16.h>
#include <cstdint>

// costs[0,i,j] = 0.5*(|x_i|^2 + |y_j|^2) - x_i . y_j
// x: [1,4096,128] f32, y: [1,4096,128] f32, out: [1,4096,4096] f32.
//
// bf16 mma.sync m16n8k16 + ldmatrix, swizzled smem, pre-converted bf16
// operands, 256 thr / 8 warps x (64x32), 2 CTAs/SM, one-shot cp.async fill,
// register-lean software-pipelined mainloop (double-buffered B, per-ti A).

#define NROWS 4096
#define DK    128
#define TILE  128

static __device__ float g_x2[NROWS];
static __device__ float g_y2[NROWS];
static __device__ __align__(16) __nv_bfloat16 g_xb[NROWS * DK];
static __device__ __align__(16) __nv_bfloat16 g_yb[NROWS * DK];

// ---- helpers ----
__device__ __forceinline__ uint32_t pack_bf16x2(float a, float b) {
    uint32_t r;
    asm("cvt.rn.bf16x2.f32 %0, %1, %2;" : "=r"(r) : "f"(b), "f"(a));
    return r;
}

__device__ __forceinline__ uint32_t smem_u32(const void* p) {
    uint32_t a;
    asm("{ .reg .u64 t; cvta.to.shared.u64 t, %1; cvt.u32.u64 %0, t; }" : "=r"(a) : "l"(p));
    return a;
}

__device__ __forceinline__ void ldsm4(uint32_t* r, uint32_t addr) {
    asm volatile("ldmatrix.sync.aligned.m8n8.x4.shared.b16 {%0,%1,%2,%3}, [%4];"
                 : "=r"(r[0]), "=r"(r[1]), "=r"(r[2]), "=r"(r[3]) : "r"(addr));
}

__device__ __forceinline__ void mma16(float* d, const uint32_t* a, uint32_t b0, uint32_t b1) {
    asm volatile(
        "mma.sync.aligned.m16n8k16.row.col.f32.bf16.bf16.f32 "
        "{%0,%1,%2,%3}, {%4,%5,%6,%7}, {%8,%9}, {%0,%1,%2,%3};"
        : "+f"(d[0]), "+f"(d[1]), "+f"(d[2]), "+f"(d[3])
        : "r"(a[0]), "r"(a[1]), "r"(a[2]), "r"(a[3]), "r"(b0), "r"(b1));
}

__device__ __forceinline__ void cp16(uint32_t dst, const void* src) {
    asm volatile("cp.async.cg.shared.global [%0], [%1], 16;" :: "r"(dst), "l"(src) : "memory");
}

// ---- smem layout (bytes) ----
#define SM_YS    0
#define SM_A     512
#define SM_B     (512 + TILE * 256)
#define SM_TOTAL (512 + 2 * TILE * 256)

// ---- pre-kernel: row norms + bf16 conversion (one pass) ----
__global__ void prep_kernel(const float* __restrict__ x, const float* __restrict__ y) {
    int gid = blockIdx.x * blockDim.x + threadIdx.x;
    int row = gid >> 5;
    int lane = gid & 31;
    bool isx = row < NROWS;
    int r = isx ? row : row - NROWS;
    const float4 v = ((const float4*)(isx ? x : y))[(size_t)r * 32 + lane];
    float s = v.x * v.x + v.y * v.y + v.z * v.z + v.w * v.w;
#pragma unroll
    for (int o = 16; o; o >>= 1) s += __shfl_xor_sync(0xffffffffu, s, o);
    uint2 w;
    w.x = pack_bf16x2(v.x, v.y);
    w.y = pack_bf16x2(v.z, v.w);
    ((uint2*)(isx ? g_xb : g_yb))[(size_t)r * 32 + lane] = w;
    if (lane == 0) { if (isx) g_x2[r] = s; else g_y2[r] = s; }
}

// ---- main kernel: 128x128 tile/CTA, 8 warps (2M x 4N of 64x32) ----
__global__ void __launch_bounds__(256, 2)
cost_kernel(float* __restrict__ out) {
    extern __shared__ char smem[];
    float* ys = (float*)(smem + SM_YS);
    const uint32_t smem_base = smem_u32(smem);

    const int tid = threadIdx.x;
    const int wid = tid >> 5;
    const int lane = tid & 31;

    const int m0 = blockIdx.y * TILE;
    const int n0 = blockIdx.x * TILE;

    if (tid < 128) ys[tid] = 0.5f * g_y2[n0 + tid];

    // One-shot fill via cp.async: 4096 16B units, 256 thr -> 16 each.
#pragma unroll
    for (int it = 0; it < 16; it++) {
        int flat = tid + 256 * it;                 // 0..4095
        int isB  = flat >> 11;
        int u    = flat & 2047;
        int row  = u >> 4;                         // 0..127
        int cu   = u & 15;
        const uint4* src = (const uint4*)(isB ? g_yb : g_xb)
                           + (size_t)((isB ? n0 : m0) + row) * 16 + cu;
        uint32_t dst = smem_base + (isB ? SM_B : SM_A) + row * 256 + ((cu ^ (row & 7)) << 4);
        cp16(dst, src);
    }
    asm volatile("cp.async.commit_group;" ::: "memory");
    asm volatile("cp.async.wait_group 0;" ::: "memory");
    __syncthreads();

    // Warp tiling: w_m 0..1 (64 rows), w_n 0..3 (32 cols)
    const int w_m = wid >> 2, w_n = wid & 3;

    const int a_row0 = w_m * 64 + (lane & 7) + ((lane >> 3) & 1) * 8;
    const int a_sel  = lane >> 4;
    const int b_row0 = w_n * 32 + (lane & 7) + (lane >> 4) * 8;
    const int b_sel  = (lane >> 3) & 1;

    const uint32_t aBase = smem_base + SM_A + a_row0 * 256;
    const uint32_t bBase0 = smem_base + SM_B + b_row0 * 256;
    const uint32_t bBase1 = bBase0 + 16 * 256;
    const int a_ph = a_row0 & 7;
    const int b_ph = b_row0 & 7;

    float acc[4][4][4];
#pragma unroll
    for (int ti = 0; ti < 4; ti++)
#pragma unroll
        for (int j = 0; j < 4; j++)
#pragma unroll
            for (int r = 0; r < 4; r++) acc[ti][j][r] = 0.f;

    // Register-lean pipelined mainloop.
    uint32_t b0[4], b1[4], b0n[4], b1n[4];
    uint32_t a_cur[4], a_nxt[4];
    {
        const uint32_t boff0 = (uint32_t)(((0 + b_sel) ^ b_ph) << 4);
        ldsm4(b0, bBase0 + boff0);
        ldsm4(b1, bBase1 + boff0);
        const uint32_t aoff0 = (uint32_t)(((0 + a_sel) ^ a_ph) << 4);
        ldsm4(a_cur, aBase + aoff0);
    }
#pragma unroll
    for (int ks = 0; ks < 8; ks++) {
        const uint32_t aoff = (uint32_t)(((ks * 2 + a_sel) ^ a_ph) << 4);
        // prefetch next ks's B frags
        if (ks < 7) {
            const uint32_t boffn = (uint32_t)((((ks + 1) * 2 + b_sel) ^ b_ph) << 4);
            ldsm4(b0n, bBase0 + boffn);
            ldsm4(b1n, bBase1 + boffn);
        }
#pragma unroll
        for (int ti = 0; ti < 4; ti++) {
            // prefetch next A frag (next ti, or ti=0 of next ks)
            if (ti < 3) {
                ldsm4(a_nxt, aBase + (ti + 1) * (16 * 256) + aoff);
            } else if (ks < 7) {
                const uint32_t aoffn = (uint32_t)((((ks + 1) * 2 + a_sel) ^ a_ph) << 4);
                ldsm4(a_nxt, aBase + aoffn);
            }
            mma16(acc[ti][0], a_cur, b0[0], b0[1]);
            mma16(acc[ti][1], a_cur, b0[2], b0[3]);
            mma16(acc[ti][2], a_cur, b1[0], b1[1]);
            mma16(acc[ti][3], a_cur, b1[2], b1[3]);
#pragma unroll
            for (int q = 0; q < 4; q++) a_cur[q] = a_nxt[q];
        }
#pragma unroll
        for (int q = 0; q < 4; q++) { b0[q] = b0n[q]; b1[q] = b1n[q]; }
    }

    // Epilogue: acc[ti][j] -> rows w_m*64+ti*16+{0,8}+gid, cols w_n*32+j*8+2*tig
    const int gid = lane >> 2, tig = lane & 3;
    const int mrow_base = m0 + w_m * 64;

#pragma unroll
    for (int ti = 0; ti < 4; ti++) {
#pragma unroll
        for (int h = 0; h < 2; h++) {
            const int m = mrow_base + ti * 16 + h * 8 + gid;
            const float xv = 0.5f * g_x2[m];
            float* orow = out + (size_t)m * NROWS + n0 + w_n * 32 + tig * 2;
#pragma unroll
            for (int j = 0; j < 4; j++) {
                const int col = w_n * 32 + j * 8 + tig * 2;
                float2 o;
                o.x = xv + ys[col + 0] - acc[ti][j][h * 2 + 0];
                o.y = xv + ys[col + 1] - acc[ti][j][h * 2 + 1];
                *(float2*)(orow + j * 8) = o;
            }
        }
    }
}

// ---- launch ----
extern "C" void kernel_launch(void* const* d_in, const int* in_sizes, int n_in,
                              void* d_out, int out_size) {
    const float* x = (const float*)d_in[0];
    const float* y = (const float*)d_in[1];
    float* out = (float*)d_out;

    cudaFuncSetAttribute(cost_kernel, cudaFuncAttributeMaxDynamicSharedMemorySize, SM_TOTAL);

    prep_kernel<<<(2 * NROWS * 32) / 256, 256>>>(x, y);
    dim3 grid(NROWS / TILE, NROWS / TILE);
    cost_kernel<<<grid, 256, SM_TOTAL>>>(out);
}